// round 1
// baseline (speedup 1.0000x reference)
#include <cuda_runtime.h>
#include <math.h>

#define D 4096
#define K2 8192
#define KS 32          // split-K chunks
#define KC (K2 / KS)   // 256 rows per chunk

// ---------------- scratch (no allocation allowed) ----------------
__device__ float    g_concat[K2];               // quantized [h, x]
__device__ float    g_partial[4 * KS * D];      // split-K partial sums (2 MB)
__device__ float    g_pre[4 * D];               // per-gate matmul results
__device__ unsigned g_gmax[4];                  // per-gate max|pre| as float bits

// ---------------- helpers ----------------
__device__ __forceinline__ float mkscale(float maxabs) {
    // matches jnp.where(max_abs > 0, max_abs / 127.0, 1.0) in fp32
    return (maxabs > 0.0f) ? (maxabs / 127.0f) : 1.0f;
}

__device__ __forceinline__ float qval(float x, float scale) {
    // clip(round(x/scale), -127, 127) * scale ; rintf = round-half-even = jnp.round
    float r = rintf(x / scale);
    r = fminf(fmaxf(r, -127.0f), 127.0f);
    return r * scale;
}

// Block-wide max of nonnegative values. Works for blockDim.x in {256, 1024}.
__device__ __forceinline__ float blockMax(float v) {
    __shared__ float s[32];
    const unsigned full = 0xffffffffu;
    #pragma unroll
    for (int o = 16; o; o >>= 1) v = fmaxf(v, __shfl_xor_sync(full, v, o));
    int lane = threadIdx.x & 31;
    int w    = threadIdx.x >> 5;
    int nw   = (blockDim.x + 31) >> 5;
    if (lane == 0) s[w] = v;
    __syncthreads();
    if (w == 0) {
        float r = (lane < nw) ? s[lane] : 0.0f;
        #pragma unroll
        for (int o = 16; o; o >>= 1) r = fmaxf(r, __shfl_xor_sync(full, r, o));
        if (lane == 0) s[0] = r;
    }
    __syncthreads();
    float out = s[0];
    __syncthreads();   // safe for back-to-back calls
    return out;
}

// ---------------- kernel 1: quantize concat = Q([h, x]), reset gate maxes ----------------
__global__ void prep_kernel(const float* __restrict__ x, const float* __restrict__ h) {
    int tid = threadIdx.x;                  // 1024 threads
    if (tid < 4) g_gmax[tid] = 0u;
    float v[8];
    float lm = 0.0f;
    #pragma unroll
    for (int j = 0; j < 8; j++) {
        int i = tid + j * 1024;             // 0..8191
        float val = (i < D) ? h[i] : x[i - D];
        v[j] = val;
        lm = fmaxf(lm, fabsf(val));
    }
    float scale = mkscale(blockMax(lm));
    #pragma unroll
    for (int j = 0; j < 8; j++) g_concat[tid + j * 1024] = qval(v[j], scale);
}

// ---------------- kernel 2: split-K GEMV partials (HBM-bound streamer) ----------------
__global__ void __launch_bounds__(256) gemv_partial_kernel(
    const float* __restrict__ Wf, const float* __restrict__ Wi,
    const float* __restrict__ Wc, const float* __restrict__ Wo)
{
    __shared__ float xs[KC];
    const int g  = blockIdx.z;                              // gate
    const int kc = blockIdx.y;                              // k-chunk
    const int n0 = blockIdx.x * 1024 + threadIdx.x * 4;     // 4 cols per thread
    const int k0 = kc * KC;

    const float* W = (g == 0) ? Wf : (g == 1) ? Wi : (g == 2) ? Wc : Wo;

    for (int i = threadIdx.x; i < KC; i += 256) xs[i] = g_concat[k0 + i];
    __syncthreads();

    const float4* p = reinterpret_cast<const float4*>(W + (size_t)k0 * D + n0);
    const int rowstride = D / 4;

    float4 acc = make_float4(0.f, 0.f, 0.f, 0.f);
    #pragma unroll 8
    for (int i = 0; i < KC; i++) {
        float4 w = p[(size_t)i * rowstride];
        float  xv = xs[i];
        acc.x = fmaf(xv, w.x, acc.x);
        acc.y = fmaf(xv, w.y, acc.y);
        acc.z = fmaf(xv, w.z, acc.z);
        acc.w = fmaf(xv, w.w, acc.w);
    }
    *reinterpret_cast<float4*>(&g_partial[(size_t)(g * KS + kc) * D + n0]) = acc;
}

// ---------------- kernel 3: split-K reduce + per-gate max_abs ----------------
__global__ void reduce_pre_kernel() {
    int i = blockIdx.x * blockDim.x + threadIdx.x;   // 0..16383; 256/block, 64 blocks
    int g = i >> 12;                                  // all threads in a block: same gate
    int n = i & (D - 1);
    float s = 0.0f;
    #pragma unroll
    for (int ks = 0; ks < KS; ks++)
        s += g_partial[(size_t)(g * KS + ks) * D + n];
    g_pre[i] = s;
    float m = blockMax(fabsf(s));
    if (threadIdx.x == 0)
        atomicMax(&g_gmax[g], __float_as_uint(m));    // order-independent -> deterministic
}

// ---------------- kernel 4: full quantized LSTM epilogue (one block) ----------------
__global__ void epilogue_kernel(const float* __restrict__ c_in,
                                const float* __restrict__ bf, const float* __restrict__ bi,
                                const float* __restrict__ bc, const float* __restrict__ bo,
                                float* __restrict__ out)
{
    const int tid = threadIdx.x;   // 1024 threads, 4 elems each (stride 1024)
    const float* bs[4] = { bf, bi, bc, bo };

    float qa[4][4];                // quantized activations per gate (f, i, c, o)

    for (int g = 0; g < 4; g++) {
        float sm = mkscale(__uint_as_float(g_gmax[g]));

        float v[4], b[4];
        float lb = 0.0f;
        #pragma unroll
        for (int j = 0; j < 4; j++) {
            int n = tid + j * 1024;
            v[j] = g_pre[g * D + n];
            b[j] = bs[g][n];
            lb = fmaxf(lb, fabsf(b[j]));
        }
        float sb = mkscale(blockMax(lb));

        float y[4];
        float ly = 0.0f;
        #pragma unroll
        for (int j = 0; j < 4; j++) {
            y[j] = qval(v[j], sm) + qval(b[j], sb);   // Q(x@w) + Q(b)
            ly = fmaxf(ly, fabsf(y[j]));
        }
        float sy = mkscale(blockMax(ly));

        float a[4];
        float la = 0.0f;
        #pragma unroll
        for (int j = 0; j < 4; j++) {
            float yq = qval(y[j], sy);                // Q(Q(x@w)+Q(b))
            a[j] = (g == 2) ? tanhf(yq) : (1.0f / (1.0f + expf(-yq)));
            la = fmaxf(la, fabsf(a[j]));
        }
        float sa = mkscale(blockMax(la));
        #pragma unroll
        for (int j = 0; j < 4; j++) qa[g][j] = qval(a[j], sa);  // Q(act)
    }

    // memory = Q(z * zi)   (z = gate 2, zi = gate 1)
    float mem[4]; float lm = 0.0f;
    #pragma unroll
    for (int j = 0; j < 4; j++) { mem[j] = qa[2][j] * qa[1][j]; lm = fmaxf(lm, fabsf(mem[j])); }
    float s = mkscale(blockMax(lm));
    #pragma unroll
    for (int j = 0; j < 4; j++) mem[j] = qval(mem[j], s);

    // cf = Q(c * zf)   (zf = gate 0)
    float cq[4]; float lc = 0.0f;
    #pragma unroll
    for (int j = 0; j < 4; j++) {
        float cf = c_in[tid + j * 1024] * qa[0][j];
        cq[j] = cf; lc = fmaxf(lc, fabsf(cf));
    }
    s = mkscale(blockMax(lc));
    #pragma unroll
    for (int j = 0; j < 4; j++) cq[j] = qval(cq[j], s);

    // c_new = Q(cf + memory)
    float cn[4]; float ln = 0.0f;
    #pragma unroll
    for (int j = 0; j < 4; j++) { cn[j] = cq[j] + mem[j]; ln = fmaxf(ln, fabsf(cn[j])); }
    s = mkscale(blockMax(ln));
    #pragma unroll
    for (int j = 0; j < 4; j++) cn[j] = qval(cn[j], s);

    // t = Q(tanh(c_new))
    float tq[4]; float lt = 0.0f;
    #pragma unroll
    for (int j = 0; j < 4; j++) { tq[j] = tanhf(cn[j]); lt = fmaxf(lt, fabsf(tq[j])); }
    s = mkscale(blockMax(lt));
    #pragma unroll
    for (int j = 0; j < 4; j++) tq[j] = qval(tq[j], s);

    // h_new = Q(zo * t)   (zo = gate 3)
    float hv[4]; float lh = 0.0f;
    #pragma unroll
    for (int j = 0; j < 4; j++) { hv[j] = qa[3][j] * tq[j]; lh = fmaxf(lh, fabsf(hv[j])); }
    s = mkscale(blockMax(lh));
    #pragma unroll
    for (int j = 0; j < 4; j++) out[tid + j * 1024] = qval(hv[j], s);
}

// ---------------- launch ----------------
extern "C" void kernel_launch(void* const* d_in, const int* in_sizes, int n_in,
                              void* d_out, int out_size)
{
    const float* x  = (const float*)d_in[0];   // inputs (1, 4096)
    const float* c  = (const float*)d_in[1];   // c      (1, 4096)
    const float* h  = (const float*)d_in[2];   // h      (1, 4096)
    const float* Wf = (const float*)d_in[3];   // (8192, 4096)
    const float* bf = (const float*)d_in[4];   // (4096,)
    const float* Wi = (const float*)d_in[5];
    const float* bi = (const float*)d_in[6];
    const float* Wc = (const float*)d_in[7];
    const float* bc = (const float*)d_in[8];
    const float* Wo = (const float*)d_in[9];
    const float* bo = (const float*)d_in[10];

    prep_kernel<<<1, 1024>>>(x, h);

    dim3 gridB(D / 1024, KS, 4);               // (4, 32, 4) = 512 blocks
    gemv_partial_kernel<<<gridB, 256>>>(Wf, Wi, Wc, Wo);

    reduce_pre_kernel<<<(4 * D) / 256, 256>>>();

    epilogue_kernel<<<1, 1024>>>(c, bf, bi, bc, bo, (float*)d_out);
}

// round 2
// speedup vs baseline: 1.1402x; 1.1402x over previous
#include <cuda_runtime.h>
#include <math.h>

#define D 4096
#define K2 8192
#define KS 32          // split-K chunks
#define KC (K2 / KS)   // 256 rows per chunk

// ---------------- scratch (no device allocation allowed) ----------------
__device__ float g_concat[K2];            // quantized [h, x]
__device__ float g_partial[4 * KS * D];   // split-K partial sums (2 MB, L2-resident)
__device__ float g_qa[4 * D];             // quantized gate activations (f, i, c, o)

// ---------------- helpers ----------------
__device__ __forceinline__ float mkscale(float maxabs) {
    // matches jnp.where(max_abs > 0, max_abs / 127.0, 1.0) in fp32
    return (maxabs > 0.0f) ? (maxabs / 127.0f) : 1.0f;
}

__device__ __forceinline__ float qval(float x, float scale) {
    // clip(round(x/scale), -127, 127) * scale ; rintf = round-half-even = jnp.round
    float r = rintf(x / scale);
    r = fminf(fmaxf(r, -127.0f), 127.0f);
    return r * scale;
}

__device__ __forceinline__ float sigm(float x) {
    return 1.0f / (1.0f + expf(-x));
}

// Block-wide max (signed-safe: pads with -INF). blockDim.x multiple of 32.
__device__ __forceinline__ float blockMax(float v) {
    __shared__ float s[32];
    const unsigned full = 0xffffffffu;
    #pragma unroll
    for (int o = 16; o; o >>= 1) v = fmaxf(v, __shfl_xor_sync(full, v, o));
    int lane = threadIdx.x & 31;
    int w    = threadIdx.x >> 5;
    int nw   = (blockDim.x + 31) >> 5;
    if (lane == 0) s[w] = v;
    __syncthreads();
    if (w == 0) {
        float r = (lane < nw) ? s[lane] : -INFINITY;
        #pragma unroll
        for (int o = 16; o; o >>= 1) r = fmaxf(r, __shfl_xor_sync(full, r, o));
        if (lane == 0) s[0] = r;
    }
    __syncthreads();
    float out = s[0];
    __syncthreads();   // safe for back-to-back calls
    return out;
}

__device__ __forceinline__ float max4abs(float4 v) {
    return fmaxf(fmaxf(fabsf(v.x), fabsf(v.y)), fmaxf(fabsf(v.z), fabsf(v.w)));
}

// ---------------- kernel 1: quantize concat = Q([h, x]) ----------------
__global__ void prep_kernel(const float* __restrict__ x, const float* __restrict__ h) {
    int tid = threadIdx.x;                  // 1024 threads
    float v[8];
    float lm = 0.0f;
    #pragma unroll
    for (int j = 0; j < 8; j++) {
        int i = tid + j * 1024;             // 0..8191
        float val = (i < D) ? h[i] : x[i - D];
        v[j] = val;
        lm = fmaxf(lm, fabsf(val));
    }
    float scale = mkscale(blockMax(lm));
    #pragma unroll
    for (int j = 0; j < 8; j++) g_concat[tid + j * 1024] = qval(v[j], scale);
}

// ---------------- kernel 2: split-K GEMV partials (HBM-bound streamer) ----------------
__global__ void __launch_bounds__(256) gemv_partial_kernel(
    const float* __restrict__ Wf, const float* __restrict__ Wi,
    const float* __restrict__ Wc, const float* __restrict__ Wo)
{
    __shared__ float xs[KC];
    const int g  = blockIdx.z;                              // gate
    const int kc = blockIdx.y;                              // k-chunk
    const int n0 = blockIdx.x * 1024 + threadIdx.x * 4;     // 4 cols per thread
    const int k0 = kc * KC;

    const float* W = (g == 0) ? Wf : (g == 1) ? Wi : (g == 2) ? Wc : Wo;

    for (int i = threadIdx.x; i < KC; i += 256) xs[i] = g_concat[k0 + i];
    __syncthreads();

    const float4* p = reinterpret_cast<const float4*>(W + (size_t)k0 * D + n0);
    const int rowstride = D / 4;

    float4 acc = make_float4(0.f, 0.f, 0.f, 0.f);
    #pragma unroll 8
    for (int i = 0; i < KC; i++) {
        float4 w = __ldcs(p + (size_t)i * rowstride);   // streaming: read-once weights
        float  xv = xs[i];
        acc.x = fmaf(xv, w.x, acc.x);
        acc.y = fmaf(xv, w.y, acc.y);
        acc.z = fmaf(xv, w.z, acc.z);
        acc.w = fmaf(xv, w.w, acc.w);
    }
    *reinterpret_cast<float4*>(&g_partial[(size_t)(g * KS + kc) * D + n0]) = acc;
}

// ---------------- kernel 3: per-gate fused reduce + quantized linear + activation ----
// grid = 4 blocks (one per gate), 1024 threads, 4 consecutive elements per thread.
__global__ void gate_kernel(const float* __restrict__ bf, const float* __restrict__ bi,
                            const float* __restrict__ bc, const float* __restrict__ bo)
{
    const int g  = blockIdx.x;
    const int n0 = threadIdx.x * 4;
    const float* b = (g == 0) ? bf : (g == 1) ? bi : (g == 2) ? bc : bo;

    // split-K reduce (L2-resident partials), fully in registers
    const float4* pp = reinterpret_cast<const float4*>(g_partial) + (size_t)g * KS * (D / 4)
                       + threadIdx.x;
    float4 acc = make_float4(0.f, 0.f, 0.f, 0.f);
    #pragma unroll
    for (int ks = 0; ks < KS; ks++) {
        float4 v = pp[(size_t)ks * (D / 4)];
        acc.x += v.x; acc.y += v.y; acc.z += v.z; acc.w += v.w;
    }
    float sm = mkscale(blockMax(max4abs(acc)));                 // Q(x@w) scale

    float4 bv = reinterpret_cast<const float4*>(b)[threadIdx.x];
    float sb = mkscale(blockMax(max4abs(bv)));                  // Q(b) scale

    // y = Q(x@w) + Q(b)
    float y[4] = { qval(acc.x, sm) + qval(bv.x, sb),
                   qval(acc.y, sm) + qval(bv.y, sb),
                   qval(acc.z, sm) + qval(bv.z, sb),
                   qval(acc.w, sm) + qval(bv.w, sb) };

    float lmax = fmaxf(fmaxf(y[0], y[1]), fmaxf(y[2], y[3]));
    float lmin = fminf(fminf(y[0], y[1]), fminf(y[2], y[3]));
    float ymax = blockMax(lmax);            // signed max of y
    float ynmx = blockMax(-lmin);           // = -min(y)
    float sy   = mkscale(fmaxf(ymax, ynmx));

    // activation + analytic activation scale (monotone functions)
    float sa;
    if (g == 2) {
        // tanh: max|tanh(yq)| = tanh(max|yq|), |qval| commutes with abs (odd fn)
        sa = mkscale(tanhf(qval(fmaxf(ymax, ynmx), sy)));
    } else {
        // sigmoid: >0 and increasing -> max = sigmoid(max yq) = sigmoid(qval(max y))
        sa = mkscale(sigm(qval(ymax, sy)));
    }

    float4 qa;
    float* qp = &qa.x;
    #pragma unroll
    for (int j = 0; j < 4; j++) {
        float yq = qval(y[j], sy);                       // Q(Q(x@w)+Q(b))
        float a  = (g == 2) ? tanhf(yq) : sigm(yq);
        qp[j] = qval(a, sa);                             // Q(activation)
    }
    reinterpret_cast<float4*>(g_qa)[(size_t)g * (D / 4) + threadIdx.x] = qa;
}

// ---------------- kernel 4: LSTM state update tail (1 block) ----------------
__global__ void tail_kernel(const float* __restrict__ c_in, float* __restrict__ out)
{
    const int t = threadIdx.x;   // 1024 threads, 4 consecutive elems each
    const float4* qa4 = reinterpret_cast<const float4*>(g_qa);
    float4 zf = qa4[0 * (D / 4) + t];
    float4 zi = qa4[1 * (D / 4) + t];
    float4 z  = qa4[2 * (D / 4) + t];
    float4 zo = qa4[3 * (D / 4) + t];
    float4 cv = reinterpret_cast<const float4*>(c_in)[t];

    float mem[4] = { z.x * zi.x, z.y * zi.y, z.z * zi.z, z.w * zi.w };
    float cf [4] = { cv.x * zf.x, cv.y * zf.y, cv.z * zf.z, cv.w * zf.w };

    float lm = 0.f, lc = 0.f;
    #pragma unroll
    for (int j = 0; j < 4; j++) { lm = fmaxf(lm, fabsf(mem[j])); lc = fmaxf(lc, fabsf(cf[j])); }
    float s_mem = mkscale(blockMax(lm));
    float s_cf  = mkscale(blockMax(lc));

    float cn[4]; float ln = 0.f;
    #pragma unroll
    for (int j = 0; j < 4; j++) {
        cn[j] = qval(cf[j], s_cf) + qval(mem[j], s_mem);   // Q(c*zf) + Q(z*zi)
        ln = fmaxf(ln, fabsf(cn[j]));
    }
    float cnmax = blockMax(ln);
    float s_cn  = mkscale(cnmax);

    // t-scale analytic: max|tanh(Q(cn))| = tanh(Q(max|cn|))
    float s_t = mkscale(tanhf(qval(cnmax, s_cn)));

    float zop[4] = { zo.x, zo.y, zo.z, zo.w };
    float hv[4]; float lh = 0.f;
    #pragma unroll
    for (int j = 0; j < 4; j++) {
        float cq = qval(cn[j], s_cn);                      // c_new
        float tq = qval(tanhf(cq), s_t);                   // Q(tanh(c_new))
        hv[j] = zop[j] * tq;
        lh = fmaxf(lh, fabsf(hv[j]));
    }
    float s_h = mkscale(blockMax(lh));

    float4 o;
    o.x = qval(hv[0], s_h); o.y = qval(hv[1], s_h);
    o.z = qval(hv[2], s_h); o.w = qval(hv[3], s_h);
    reinterpret_cast<float4*>(out)[t] = o;
}

// ---------------- launch ----------------
extern "C" void kernel_launch(void* const* d_in, const int* in_sizes, int n_in,
                              void* d_out, int out_size)
{
    const float* x  = (const float*)d_in[0];   // inputs (1, 4096)
    const float* c  = (const float*)d_in[1];   // c      (1, 4096)
    const float* h  = (const float*)d_in[2];   // h      (1, 4096)
    const float* Wf = (const float*)d_in[3];   // (8192, 4096)
    const float* bf = (const float*)d_in[4];   // (4096,)
    const float* Wi = (const float*)d_in[5];
    const float* bi = (const float*)d_in[6];
    const float* Wc = (const float*)d_in[7];
    const float* bc = (const float*)d_in[8];
    const float* Wo = (const float*)d_in[9];
    const float* bo = (const float*)d_in[10];

    prep_kernel<<<1, 1024>>>(x, h);

    dim3 gridB(D / 1024, KS, 4);               // (4, 32, 4) = 512 blocks
    gemv_partial_kernel<<<gridB, 256>>>(Wf, Wi, Wc, Wo);

    gate_kernel<<<4, 1024>>>(bf, bi, bc, bo);

    tail_kernel<<<1, 1024>>>(c, (float*)d_out);
}